// round 10
// baseline (speedup 1.0000x reference)
#include <cuda_runtime.h>
#include <cuda_fp16.h>
#include <cstdint>
#include <cstddef>

#define KDIM 256
#define NQ_  1024
#define B_   4
#define NF_  65536

// scratch (__device__ globals: the sanctioned no-alloc path)
__device__ __half g_wh[4 * KDIM * KDIM];   // fp16 weights, [layer][out][in]
__device__ __half g_qh[NQ_ * KDIM];        // fp16 MLP output (logits B operand)

__device__ __forceinline__ uint32_t cvta_s(const void* p) {
    return (uint32_t)__cvta_generic_to_shared(p);
}

#define LDM4(r0, r1, r2, r3, addr) \
    asm volatile("ldmatrix.sync.aligned.m8n8.x4.shared.b16 {%0,%1,%2,%3}, [%4];" \
                 : "=r"(r0), "=r"(r1), "=r"(r2), "=r"(r3) : "r"(addr))

#define MMA16(c, a, b0, b1) \
    asm volatile("mma.sync.aligned.m16n8k16.row.col.f32.f16.f16.f32 " \
                 "{%0,%1,%2,%3},{%4,%5,%6,%7},{%8,%9},{%0,%1,%2,%3};" \
                 : "+f"((c)[0]), "+f"((c)[1]), "+f"((c)[2]), "+f"((c)[3]) \
                 : "r"((a)[0]), "r"((a)[1]), "r"((a)[2]), "r"((a)[3]), "r"(b0), "r"(b1))

#define CP16(dst, src) \
    asm volatile("cp.async.cg.shared.global [%0], [%1], 16;" :: "r"(dst), "l"(src))

// ---------------------------------------------------------------------------
// prep: convert the 4 weight matrices f32 -> fp16 (once per launch)
// ---------------------------------------------------------------------------
__global__ void prep_w(const float* __restrict__ W1, const float* __restrict__ W2,
                       const float* __restrict__ W3, const float* __restrict__ W4)
{
    int idx = blockIdx.x * 256 + threadIdx.x;          // 65536 float4 total
    const float* src = (idx < 16384) ? W1 : (idx < 32768) ? W2 : (idx < 49152) ? W3 : W4;
    int off = idx & 16383;
    float4 v = ((const float4*)src)[off];
    __half2 h0 = __floats2half2_rn(v.x, v.y);
    __half2 h1 = __floats2half2_rn(v.z, v.w);
    uint2 u;
    u.x = *(uint32_t*)&h0;
    u.y = *(uint32_t*)&h1;
    ((uint2*)g_wh)[idx] = u;
}

// ---------------------------------------------------------------------------
// Fused 4-layer MLP (unchanged; ~10us)
// ---------------------------------------------------------------------------
#define MLP_SMEM (65536 + 49152 + 4096)

__global__ __launch_bounds__(256) void mlp_fused(
    const float* __restrict__ Q, const __half* __restrict__ wh,
    const float* __restrict__ b1, const float* __restrict__ b2,
    const float* __restrict__ b3, const float* __restrict__ b4,
    __half* __restrict__ qh)
{
    extern __shared__ char sm[];
    char*  xb = sm;                        // 2 x 32768
    char*  ws = sm + 65536;                // 3 x 16384
    float* sb = (float*)(sm + 65536 + 49152);

    const int tid = threadIdx.x;
    const int w = tid >> 5, l = tid & 31;
    const int g = l >> 2, t = l & 3;
    const int wm = (w & 1) * 32;
    const int wn = (w >> 1) * 64;
    const int m0 = blockIdx.x * 64;

    sb[tid] = b1[tid]; sb[256 + tid] = b2[tid];
    sb[512 + tid] = b3[tid]; sb[768 + tid] = b4[tid];

#pragma unroll
    for (int i = 0; i < 16; i++) {
        int idx = tid + i * 256;
        int r = idx >> 6, k = (idx & 63) * 4;
        float4 v = *(const float4*)&Q[(size_t)(m0 + r) * KDIM + k];
        __half2 h0 = __floats2half2_rn(v.x, v.y);
        __half2 h1 = __floats2half2_rn(v.z, v.w);
        int chunk = k >> 5, c16 = (k & 31) >> 3, hi = (k >> 2) & 1;
        uint32_t ad = cvta_s(xb + chunk * 4096 + (r & 31) * 128
                             + ((((r >> 5) * 4) + c16) ^ (r & 7)) * 16 + hi * 8);
        asm volatile("st.shared.v2.b32 [%0], {%1,%2};"
                     :: "r"(ad), "r"(*(uint32_t*)&h0), "r"(*(uint32_t*)&h1));
    }

    uint32_t b_addr[4];
    {
        int n = wn + (l & 7) + ((l >> 4) & 1) * 8;
        int ck = (l >> 3) & 1;
#pragma unroll
        for (int p = 0; p < 4; p++) {
            int nn = n + p * 16;
            int cp = (((nn >> 7) * 4 + ck) ^ (nn & 7));
            b_addr[p] = cvta_s(ws + (nn & 127) * 128 + cp * 16);
        }
    }
    uint32_t wst[4];
#pragma unroll
    for (int c = 0; c < 4; c++) {
        int n = tid;
        wst[c] = cvta_s(ws + (n & 127) * 128 + ((((n >> 7) * 4) + c) ^ (n & 7)) * 16);
    }

    __syncthreads();

    for (int L = 0; L < 4; L++) {
        const __half* Wl = wh + (size_t)L * 65536;
        const uint32_t xbase = (uint32_t)(L & 1) * 32768;

        uint32_t a_addr[2];
        {
            int r = wm + (l & 7) + ((l >> 3) & 1) * 8;
            int ck = (l >> 4) & 1;
#pragma unroll
            for (int mt = 0; mt < 2; mt++) {
                int rr = r + mt * 16;
                int cp = (((rr >> 5) * 4 + ck) ^ (rr & 7));
                a_addr[mt] = cvta_s(xb + xbase + (rr & 31) * 128 + cp * 16);
            }
        }

#pragma unroll
        for (int s = 0; s < 2; s++) {
#pragma unroll
            for (int c = 0; c < 4; c++)
                CP16(wst[c] + s * 16384, Wl + (size_t)tid * KDIM + s * 32 + c * 8);
            asm volatile("cp.async.commit_group;");
        }

        float acc[2][8][4];
#pragma unroll
        for (int mt = 0; mt < 2; mt++)
#pragma unroll
            for (int nt = 0; nt < 8; nt++)
#pragma unroll
                for (int i = 0; i < 4; i++) acc[mt][nt][i] = 0.f;

#pragma unroll
        for (int kt = 0; kt < 8; kt++) {
            asm volatile("cp.async.wait_group 1;");
            __syncthreads();
            if (kt < 6) {
                int s = (kt + 2) % 3;
#pragma unroll
                for (int c = 0; c < 4; c++)
                    CP16(wst[c] + s * 16384, Wl + (size_t)tid * KDIM + (kt + 2) * 32 + c * 8);
            }
            asm volatile("cp.async.commit_group;");

            const uint32_t abuf = kt * 4096;
            const uint32_t bbuf = (kt % 3) * 16384;
#pragma unroll
            for (int g16 = 0; g16 < 2; g16++) {
                const uint32_t xo = g16 * 32;
                uint32_t a0[4], a1[4];
                LDM4(a0[0], a0[1], a0[2], a0[3], (a_addr[0] + abuf) ^ xo);
                LDM4(a1[0], a1[1], a1[2], a1[3], (a_addr[1] + abuf) ^ xo);
                uint32_t bf[4][4];
#pragma unroll
                for (int p = 0; p < 4; p++)
                    LDM4(bf[p][0], bf[p][1], bf[p][2], bf[p][3], (b_addr[p] + bbuf) ^ xo);
#pragma unroll
                for (int nt = 0; nt < 8; nt++) {
                    uint32_t q0 = bf[nt >> 1][(nt & 1) * 2];
                    uint32_t q1 = bf[nt >> 1][(nt & 1) * 2 + 1];
                    MMA16(acc[0][nt], a0, q0, q1);
                    MMA16(acc[1][nt], a1, q0, q1);
                }
            }
        }

        __syncthreads();

        if (L < 3) {
            const uint32_t pong = (uint32_t)((L & 1) ^ 1) * 32768;
#pragma unroll
            for (int mt = 0; mt < 2; mt++) {
#pragma unroll
                for (int nt = 0; nt < 8; nt++) {
                    int r = wm + mt * 16 + g;
                    int c = wn + nt * 8 + 2 * t;
                    float bi0 = sb[L * 256 + c], bi1 = sb[L * 256 + c + 1];
                    float v0 = fmaxf(acc[mt][nt][0] + bi0, 0.f);
                    float v1 = fmaxf(acc[mt][nt][1] + bi1, 0.f);
                    float v2 = fmaxf(acc[mt][nt][2] + bi0, 0.f);
                    float v3 = fmaxf(acc[mt][nt][3] + bi1, 0.f);
                    __half2 h01 = __floats2half2_rn(v0, v1);
                    __half2 h23 = __floats2half2_rn(v2, v3);
                    int chunk = c >> 5, c16 = (c & 31) >> 3, bo = (c & 7) * 2;
                    int r8 = r + 8;
                    uint32_t ad0 = cvta_s(xb + pong + chunk * 4096 + (r & 31) * 128
                                   + ((((r >> 5) * 4) + c16) ^ (r & 7)) * 16 + bo);
                    uint32_t ad1 = cvta_s(xb + pong + chunk * 4096 + (r8 & 31) * 128
                                   + ((((r8 >> 5) * 4) + c16) ^ (r8 & 7)) * 16 + bo);
                    asm volatile("st.shared.b32 [%0], %1;" :: "r"(ad0), "r"(*(uint32_t*)&h01));
                    asm volatile("st.shared.b32 [%0], %1;" :: "r"(ad1), "r"(*(uint32_t*)&h23));
                }
            }
        } else {
#pragma unroll
            for (int mt = 0; mt < 2; mt++) {
#pragma unroll
                for (int nt = 0; nt < 8; nt++) {
                    int r = m0 + wm + mt * 16 + g;
                    int c = wn + nt * 8 + 2 * t;
                    float bi0 = sb[768 + c], bi1 = sb[768 + c + 1];
                    __half2 h01 = __floats2half2_rn(acc[mt][nt][0] + bi0, acc[mt][nt][1] + bi1);
                    __half2 h23 = __floats2half2_rn(acc[mt][nt][2] + bi0, acc[mt][nt][3] + bi1);
                    *(__half2*)&qh[(size_t)r * KDIM + c]       = h01;
                    *(__half2*)&qh[(size_t)(r + 8) * KDIM + c] = h23;
                }
            }
        }
        __syncthreads();
    }
}

// ---------------------------------------------------------------------------
// Logits GEMM v4b: persistent, CTA tile 128 x 256 (full N), warp tile 64x64.
//  - grid = 148, each CTA loops over 2048 tiles stride-148 (no wave churn)
//  - A: LDG f32 (distance-2 reg prefetch) -> cvt -> STS fp16, double buffer
//  - B: FOUR-slot cp.async ring (16KB/slot) -- prefetch distance 3 < ring 4
//    (round-9 bug: 3-slot ring + distance-3 prefetch overwrote the live slot)
//  A smem:  (r&63)*128 + ((((r>>6)*4)+c16)^(r&7))*16      (128 rows x 32k fp16)
//  B smem:  (n>>7)*8192 + (n&63)*128 + (((((n>>6)&1)*4)+c)^(n&7))*16  (256 rows)
// ---------------------------------------------------------------------------
#define LOG_SMEM (2 * 8192 + 4 * 16384)   // 81920
#define TILES    2048
#define GRID_LOG 148

__global__ __launch_bounds__(256)
void gemm_logits(const float* __restrict__ A, const __half* __restrict__ Bh,
                 float* __restrict__ C)
{
    extern __shared__ char sm[];   // [0,16K): A bufs; [16K,80K): B ring (4 slots)

    const int tid = threadIdx.x;
    const int w = tid >> 5, l = tid & 31;
    const int g = l >> 2, t = l & 3;
    const int wm = (w & 1) * 64;     // 2 m-warps
    const int wn = (w >> 1) * 64;    // 4 n-warps

    // ldmatrix A addrs (buf-relative)
    uint32_t a_addr[4];
    {
        int rbase = wm + (l & 7) + ((l >> 3) & 1) * 8;
        int ck = (l >> 4) & 1;
#pragma unroll
        for (int mt = 0; mt < 4; mt++) {
            int rr = rbase + mt * 16;
            a_addr[mt] = cvta_s(sm + (rr & 63) * 128
                                + ((((rr >> 6) * 4) + ck) ^ (rr & 7)) * 16);
        }
    }
    // ldmatrix B addrs (slot-relative, based at sm+16384)
    uint32_t b_addr[4];
    {
        int nbase = wn + (l & 7) + ((l >> 4) & 1) * 8;
        int ck = (l >> 3) & 1;
#pragma unroll
        for (int p = 0; p < 4; p++) {
            int nn = nbase + p * 16;
            b_addr[p] = cvta_s(sm + 16384 + (nn >> 7) * 8192 + (nn & 63) * 128
                               + (((((nn >> 6) & 1) * 4) + ck) ^ (nn & 7)) * 16);
        }
    }
    // A STS addrs: thread -> rows (tid>>3)+i*32, k-float-group f
    const int f = tid & 7;
    uint32_t sts_addr[4];
#pragma unroll
    for (int i = 0; i < 4; i++) {
        int r = (tid >> 3) + i * 32;
        sts_addr[i] = cvta_s(sm + (r & 63) * 128
                             + ((((r >> 6) * 4) + (f >> 1)) ^ (r & 7)) * 16 + (f & 1) * 8);
    }
    // B cp.async dsts: thread = row n=tid, 4 x 16B
    uint32_t bst[4];
#pragma unroll
    for (int c = 0; c < 4; c++) {
        int n = tid;
        bst[c] = cvta_s(sm + 16384 + (n >> 7) * 8192 + (n & 63) * 128
                        + (((((n >> 6) & 1) * 4) + c) ^ (n & 7)) * 16);
    }

    for (int tt = blockIdx.x; tt < TILES; tt += GRID_LOG) {
        const int bb = tt >> 9;          // batch
        const int mb = tt & 511;         // m-tile
        const float* Ab = A + (size_t)bb * NF_ * KDIM + (size_t)mb * 128 * KDIM;
        const __half* Bb = Bh + (size_t)bb * 256 * KDIM;
        float* Cb = C + (size_t)bb * NF_ * 256 + (size_t)mb * 128 * 256;

        const float* asrc = Ab + (size_t)(tid >> 3) * KDIM + f * 4;
        const __half* bsrc = Bb + (size_t)tid * KDIM;

        // ---- prologue: B slots 0,1,2 ; A(0),A(1) in regs ----
        float4 pre[2][4];
#pragma unroll
        for (int i = 0; i < 4; i++) pre[0][i] = *(const float4*)(asrc + (size_t)i * 32 * KDIM);
#pragma unroll
        for (int c = 0; c < 4; c++) CP16(bst[c], bsrc + c * 8);
        asm volatile("cp.async.commit_group;");
#pragma unroll
        for (int i = 0; i < 4; i++) pre[1][i] = *(const float4*)(asrc + (size_t)i * 32 * KDIM + 32);
#pragma unroll
        for (int c = 0; c < 4; c++) CP16(bst[c] + 16384, bsrc + 32 + c * 8);
        asm volatile("cp.async.commit_group;");
#pragma unroll
        for (int c = 0; c < 4; c++) CP16(bst[c] + 32768, bsrc + 64 + c * 8);
        asm volatile("cp.async.commit_group;");

        // STS A(0)
#pragma unroll
        for (int i = 0; i < 4; i++) {
            __half2 h0 = __floats2half2_rn(pre[0][i].x, pre[0][i].y);
            __half2 h1 = __floats2half2_rn(pre[0][i].z, pre[0][i].w);
            asm volatile("st.shared.v2.b32 [%0], {%1,%2};"
                         :: "r"(sts_addr[i]), "r"(*(uint32_t*)&h0), "r"(*(uint32_t*)&h1));
        }

        float acc[4][8][4];
#pragma unroll
        for (int mt = 0; mt < 4; mt++)
#pragma unroll
            for (int nt = 0; nt < 8; nt++)
#pragma unroll
                for (int i = 0; i < 4; i++) acc[mt][nt][i] = 0.f;

        asm volatile("cp.async.wait_group 2;");   // B(0) resident
        __syncthreads();

        // ---- 8 stages of BK=32 ----
#pragma unroll
        for (int kt = 0; kt < 8; kt++) {
            const uint32_t abuf = (uint32_t)(kt & 1) * 8192;
            const uint32_t bslot = (uint32_t)(kt & 3) * 16384;

            // fragments g16=0
            uint32_t af[4][4], bf[4][4];
#pragma unroll
            for (int mt = 0; mt < 4; mt++)
                LDM4(af[mt][0], af[mt][1], af[mt][2], af[mt][3], a_addr[mt] + abuf);
#pragma unroll
            for (int p = 0; p < 4; p++)
                LDM4(bf[p][0], bf[p][1], bf[p][2], bf[p][3], b_addr[p] + bslot);

            // STS A(kt+1)
            if (kt < 7) {
                const uint32_t nab = (uint32_t)((kt + 1) & 1) * 8192;
#pragma unroll
                for (int i = 0; i < 4; i++) {
                    __half2 h0 = __floats2half2_rn(pre[(kt + 1) & 1][i].x, pre[(kt + 1) & 1][i].y);
                    __half2 h1 = __floats2half2_rn(pre[(kt + 1) & 1][i].z, pre[(kt + 1) & 1][i].w);
                    asm volatile("st.shared.v2.b32 [%0], {%1,%2};"
                                 :: "r"(sts_addr[i] + nab),
                                    "r"(*(uint32_t*)&h0), "r"(*(uint32_t*)&h1));
                }
            }

            // MMA g16=0 (32 MMAs)
#pragma unroll
            for (int mt = 0; mt < 4; mt++)
#pragma unroll
                for (int nt = 0; nt < 8; nt++)
                    MMA16(acc[mt][nt], af[mt], bf[nt >> 1][(nt & 1) * 2], bf[nt >> 1][(nt & 1) * 2 + 1]);

            // fragments g16=1
#pragma unroll
            for (int mt = 0; mt < 4; mt++)
                LDM4(af[mt][0], af[mt][1], af[mt][2], af[mt][3], (a_addr[mt] + abuf) ^ 32);
#pragma unroll
            for (int p = 0; p < 4; p++)
                LDM4(bf[p][0], bf[p][1], bf[p][2], bf[p][3], (b_addr[p] + bslot) ^ 32);

            // LDG A(kt+2) into freed reg buffer
            if (kt < 6) {
#pragma unroll
                for (int i = 0; i < 4; i++)
                    pre[kt & 1][i] = *(const float4*)(asrc + (size_t)i * 32 * KDIM + (kt + 2) * 32);
            }
            // cp.async B(kt+3) into slot (kt+3)&3  (ring 4 > distance 3: no overwrite)
            if (kt < 5) {
                const uint32_t ns = (uint32_t)((kt + 3) & 3) * 16384;
#pragma unroll
                for (int c = 0; c < 4; c++)
                    CP16(bst[c] + ns, bsrc + (kt + 3) * 32 + c * 8);
            }
            asm volatile("cp.async.commit_group;");
            asm volatile("cp.async.wait_group 2;");   // B(kt+1) resident

            // MMA g16=1 (32 MMAs)
#pragma unroll
            for (int mt = 0; mt < 4; mt++)
#pragma unroll
                for (int nt = 0; nt < 8; nt++)
                    MMA16(acc[mt][nt], af[mt], bf[nt >> 1][(nt & 1) * 2], bf[nt >> 1][(nt & 1) * 2 + 1]);

            __syncthreads();
        }

        // ---- epilogue: streaming stores ----
#pragma unroll
        for (int mt = 0; mt < 4; mt++) {
            const int r0 = wm + mt * 16 + g;
#pragma unroll
            for (int nt = 0; nt < 8; nt++) {
                const int c = wn + nt * 8 + 2 * t;
                __stcs((float2*)&Cb[(size_t)r0 * 256 + c],
                       make_float2(acc[mt][nt][0], acc[mt][nt][1]));
                __stcs((float2*)&Cb[(size_t)(r0 + 8) * 256 + c],
                       make_float2(acc[mt][nt][2], acc[mt][nt][3]));
            }
        }
        // next tile's writes into A buf0 / B slot0 are ordered by the
        // stage-7 __syncthreads above (their last readers: stage 6 / stage 4).
    }
}

// ---------------------------------------------------------------------------
extern "C" void kernel_launch(void* const* d_in, const int* in_sizes, int n_in,
                              void* d_out, int out_size)
{
    (void)in_sizes; (void)n_in; (void)out_size;
    const float* queries = (const float*)d_in[0];
    const float* feats   = (const float*)d_in[1];
    const float* W1 = (const float*)d_in[4];
    const float* b1 = (const float*)d_in[5];
    const float* W2 = (const float*)d_in[6];
    const float* b2 = (const float*)d_in[7];
    const float* W3 = (const float*)d_in[8];
    const float* b3 = (const float*)d_in[9];
    const float* W4 = (const float*)d_in[10];
    const float* b4 = (const float*)d_in[11];
    float* out = (float*)d_out;

    __half *wh = nullptr, *qh = nullptr;
    cudaGetSymbolAddress((void**)&wh, g_wh);
    cudaGetSymbolAddress((void**)&qh, g_qh);

    cudaFuncSetAttribute(mlp_fused,   cudaFuncAttributeMaxDynamicSharedMemorySize, MLP_SMEM);
    cudaFuncSetAttribute(gemm_logits, cudaFuncAttributeMaxDynamicSharedMemorySize, LOG_SMEM);

    prep_w<<<256, 256>>>(W1, W2, W3, W4);
    mlp_fused<<<16, 256, MLP_SMEM>>>(queries, wh, b1, b2, b3, b4, qh);
    gemm_logits<<<GRID_LOG, 256, LOG_SMEM>>>(feats, qh, out);
}